// round 12
// baseline (speedup 1.0000x reference)
#include <cuda_runtime.h>
#include <cuda_fp16.h>
#include <cstdint>
#include <math.h>

// ---------------- problem dims ----------------
#define BB   64
#define NN   512
#define MD   1024
#define AD   1024
#define ROWS (BB * NN)          // 32768

// ---------------- GEMM tiling ----------------
#define MT 128                  // M per CTA
#define NT 128                  // N per CTA
#define KC 64                   // K elems per chunk (64 fp16 = 128 B rows)
#define NCHUNK (MD / KC)        // 16

// stage: A 16K | B 16K
#define ST_A  0
#define ST_B  16384
#define STAGE_BYTES 32768
#define NSTAGE 3
#define SMEM_TOTAL (NSTAGE * STAGE_BYTES)   // 96 KB; 2 CTAs/SM -> 192 KB

// XOR swizzle for 128-byte rows (conflict-free ldmatrix + cp.async stores)
#define SWZ(x) ((x) ^ (((x) >> 3) & 0x70))

// ---------------- scratch (__device__ globals; no allocs allowed) ----------
__device__ float g_tq[BB * AD];
__device__ float g_logits[ROWS];
__device__ float g_weights[ROWS];
__device__ __half g_Ah[(size_t)ROWS * MD];   // mv rounded to fp16
__device__ __half g_Bh[(size_t)AD * MD];     // Wh^T rounded to fp16, [n][k]

// ---------------- PTX helpers (plain-sm_103-legal) ----------------
__device__ __forceinline__ uint32_t smem_u32(const void* p) {
    uint32_t a;
    asm("{ .reg .u64 t; cvta.to.shared.u64 t, %1; cvt.u32.u64 %0, t; }"
        : "=r"(a) : "l"(p));
    return a;
}
__device__ __forceinline__ void cp16(uint32_t s, const void* g) {
    asm volatile("cp.async.cg.shared.global [%0], [%1], 16;" :: "r"(s), "l"(g));
}
#define CP_COMMIT() asm volatile("cp.async.commit_group;" ::: "memory")
#define CP_WAIT1()  asm volatile("cp.async.wait_group %0;" :: "n"(1) : "memory")

#define LDSM4(r, a) \
    asm volatile("ldmatrix.sync.aligned.m8n8.x4.shared.b16 {%0,%1,%2,%3}, [%4];" \
        : "=r"((r)[0]), "=r"((r)[1]), "=r"((r)[2]), "=r"((r)[3]) : "r"(a))

#define MMA16816(d, a, b0v, b1v) \
    asm volatile("mma.sync.aligned.m16n8k16.row.col.f32.f16.f16.f32 " \
        "{%0,%1,%2,%3}, {%4,%5,%6,%7}, {%8,%9}, {%0,%1,%2,%3};" \
        : "+f"((d)[0]), "+f"((d)[1]), "+f"((d)[2]), "+f"((d)[3]) \
        : "r"((a)[0]), "r"((a)[1]), "r"((a)[2]), "r"((a)[3]), \
          "r"(b0v), "r"(b1v))

// ---------------------------------------------------------------------------
// Zero init: logits, tq (both atomic-accumulated), d_out (poisoned)
// ---------------------------------------------------------------------------
__global__ void zero_kernel(float* __restrict__ ctx) {
    int i = blockIdx.x * blockDim.x + threadIdx.x;   // 0 .. 65535
    if (i < ROWS) g_logits[i] = 0.0f;
    if (i < BB * AD) { g_tq[i] = 0.0f; ctx[i] = 0.0f; }
}

// ---------------------------------------------------------------------------
// fp32 -> fp16 round of mv
// ---------------------------------------------------------------------------
__global__ __launch_bounds__(256) void convert_mv_kernel(const float* __restrict__ mv) {
    size_t i = ((size_t)blockIdx.x * 256 + threadIdx.x) * 4;
    float4 x = *reinterpret_cast<const float4*>(mv + i);
    __half2* d = reinterpret_cast<__half2*>(g_Ah + i);
    d[0] = __floats2half2_rn(x.x, x.y);
    d[1] = __floats2half2_rn(x.z, x.w);
}

// ---------------------------------------------------------------------------
// Wh [k][n] -> Wh^T fp16 [n][k] via smem tile transpose
// ---------------------------------------------------------------------------
__global__ void whT_convert_kernel(const float* __restrict__ Wh) {
    __shared__ float t[32][33];
    int n0 = blockIdx.x * 32, k0 = blockIdx.y * 32;
    int tx = threadIdx.x, ty = threadIdx.y;          // block (32, 8)
    for (int i = ty; i < 32; i += 8)
        t[i][tx] = Wh[(size_t)(k0 + i) * AD + n0 + tx];
    __syncthreads();
    for (int i = ty; i < 32; i += 8) {
        float x = t[tx][i];                          // Wh[k0+tx][n0+i]
        g_Bh[(size_t)(n0 + i) * MD + k0 + tx] = __float2half_rn(x);
    }
}

// ---------------------------------------------------------------------------
// tq = query @ Ws.  Grid (8 k-chunks of 128, 16 batch-groups of 4).
// Each CTA reads its Ws slice ONCE and applies it to 4 batches
// (Ws L2 traffic 256 MB -> 64 MB).  atomicAdd accumulate across k-chunks.
// ---------------------------------------------------------------------------
__global__ __launch_bounds__(256) void tq_kernel(const float* __restrict__ q,
                                                 const float* __restrict__ Ws) {
    __shared__ float qs[4][128];
    const int k0 = blockIdx.x * 128;
    const int b0 = blockIdx.y * 4;

    // load q slice for 4 batches x 128 k
    {
        int idx = threadIdx.x;               // 2 loads/thread
        qs[idx >> 7][idx & 127] = q[(b0 + (idx >> 7)) * MD + k0 + (idx & 127)];
        idx += 256;
        qs[idx >> 7][idx & 127] = q[(b0 + (idx >> 7)) * MD + k0 + (idx & 127)];
    }
    __syncthreads();

    const int c = threadIdx.x;               // cols c, c+256, c+512, c+768
    float acc[4][4];
#pragma unroll
    for (int bi = 0; bi < 4; bi++)
#pragma unroll
        for (int cj = 0; cj < 4; cj++) acc[bi][cj] = 0.f;

    for (int k = 0; k < 128; k++) {
        const float* wrow = Ws + (size_t)(k0 + k) * AD + c;
        float w0 = wrow[0], w1 = wrow[256], w2 = wrow[512], w3 = wrow[768];
#pragma unroll
        for (int bi = 0; bi < 4; bi++) {
            float qv = qs[bi][k];
            acc[bi][0] += qv * w0;
            acc[bi][1] += qv * w1;
            acc[bi][2] += qv * w2;
            acc[bi][3] += qv * w3;
        }
    }
#pragma unroll
    for (int bi = 0; bi < 4; bi++) {
        float* dst = g_tq + (b0 + bi) * AD + c;
        atomicAdd(dst,       acc[bi][0]);
        atomicAdd(dst + 256, acc[bi][1]);
        atomicAdd(dst + 512, acc[bi][2]);
        atomicAdd(dst + 768, acc[bi][3]);
    }
}

// ---------------------------------------------------------------------------
// Big GEMM on HMMA fp16 (fp32 accum): D = Ah @ Bh^T.
// Fused epilogue: logits[m] += sum_n tanh(D + tq) * v[n].
// CTA 128x128 with FOUR warps (warp tile 64x64, 2m x 2n) -> smem-read
// amplification A=2/B=2 (vs 4/2 before), MMA:LDSM ratio 4.
// 3-stage cp.async pipeline, ONE __syncthreads per chunk.
// ---------------------------------------------------------------------------
__global__ __launch_bounds__(128, 2) void gemm_hmma_kernel(const float* __restrict__ v) {
    extern __shared__ char smem[];
    const uint32_t sb = smem_u32(smem);
    const int tid  = threadIdx.x;
    const int lane = tid & 31;
    const int w    = tid >> 5;               // 0..3
    const int tileN = blockIdx.x * NT;
    const int tileM = blockIdx.y * MT;

    const __half* Ag = g_Ah + (size_t)tileM * MD;
    const __half* Bg = g_Bh + (size_t)tileN * MD;

    // cp.async per-thread coords (128 threads: 16 rows x 8 cc per pass, 8 passes)
    const int cr = tid >> 3;                 // 0..15
    const int cc = tid & 7;                  // 16B unit in 128B row

    // ldmatrix invariants
    const int lrow = lane & 15;
    const int lkb  = (lane >> 4) * 16;

    // warp tile position: 2m x 2n, each 64x64
    const int wm = (w & 1) * 64;
    const int wn = (w >> 1) * 64;

    float acc[4][8][4];
#pragma unroll
    for (int i = 0; i < 4; i++)
#pragma unroll
        for (int j = 0; j < 8; j++)
#pragma unroll
            for (int cidx = 0; cidx < 4; cidx++) acc[i][j][cidx] = 0.f;

    auto issue_copy = [&](int chunk) {
        const int k0 = chunk * KC;
        const uint32_t st = sb + (chunk % NSTAGE) * STAGE_BYTES;
#pragma unroll
        for (int i = 0; i < 8; i++) {
            const int r = cr + i * 16;
            const uint32_t so = SWZ((uint32_t)(r * 128 + cc * 16));
            const size_t go = (size_t)r * MD + k0 + cc * 8;
            cp16(st + ST_A + so, Ag + go);
            cp16(st + ST_B + so, Bg + go);
        }
    };

    issue_copy(0); CP_COMMIT();
    issue_copy(1); CP_COMMIT();

    for (int c = 0; c < NCHUNK; ++c) {
        CP_WAIT1();
        __syncthreads();                     // orders prev-chunk reads before overwrite
        if (c + 2 < NCHUNK) issue_copy(c + 2);
        CP_COMMIT();                         // (possibly empty group; keeps count uniform)

        const uint32_t st = sb + (c % NSTAGE) * STAGE_BYTES;
#pragma unroll
        for (int ks = 0; ks < 4; ks++) {
            const int kb2 = ks * 32 + lkb;
            uint32_t a[4][4], b[4][4];
#pragma unroll
            for (int i = 0; i < 4; i++) {
                uint32_t ad = st + ST_A + SWZ((uint32_t)((wm + i * 16 + lrow) * 128 + kb2));
                LDSM4(a[i], ad);
            }
#pragma unroll
            for (int j = 0; j < 4; j++) {
                uint32_t ad = st + ST_B + SWZ((uint32_t)((wn + j * 16 + lrow) * 128 + kb2));
                LDSM4(b[j], ad);
            }
#pragma unroll
            for (int i = 0; i < 4; i++)
#pragma unroll
                for (int j = 0; j < 4; j++) {
                    MMA16816(acc[i][2 * j],     a[i], b[j][0], b[j][2]);
                    MMA16816(acc[i][2 * j + 1], a[i], b[j][1], b[j][3]);
                }
        }
    }

    // ---- fused epilogue: logits[m] += sum_n tanh(acc + tq[b][n]) * v[n] ----
    const int bq = (tileM / NN) * AD;
    const int rq = lane >> 2;
    const int cq = (lane & 3) * 2;

#pragma unroll
    for (int i = 0; i < 4; i++) {
        float s0 = 0.f, s1 = 0.f;
#pragma unroll
        for (int j = 0; j < 8; j++) {
            const int n0 = tileN + wn + j * 8 + cq;
            const float v0 = v[n0],          v1 = v[n0 + 1];
            const float t0 = g_tq[bq + n0],  t1 = g_tq[bq + n0 + 1];
            s0 += tanhf(acc[i][j][0] + t0) * v0 + tanhf(acc[i][j][1] + t1) * v1;
            s1 += tanhf(acc[i][j][2] + t0) * v0 + tanhf(acc[i][j][3] + t1) * v1;
        }
        s0 += __shfl_xor_sync(0xffffffffu, s0, 1);
        s0 += __shfl_xor_sync(0xffffffffu, s0, 2);
        s1 += __shfl_xor_sync(0xffffffffu, s1, 1);
        s1 += __shfl_xor_sync(0xffffffffu, s1, 2);
        if ((lane & 3) == 0) {
            const int m0 = tileM + wm + i * 16 + rq;
            atomicAdd(&g_logits[m0],     s0);
            atomicAdd(&g_logits[m0 + 8], s1);
        }
    }
}

// ---------------------------------------------------------------------------
// Masked softmax (reference semantics incl. fully-masked rows)
// ---------------------------------------------------------------------------
__global__ __launch_bounds__(NN) void softmax_kernel(const int* __restrict__ mask) {
    __shared__ float sdata[NN];
    int b = blockIdx.x, n = threadIdx.x;
    float lg = g_logits[b * NN + n];
    int   m  = mask[b * NN + n];

    int any = __syncthreads_or(m != 0);
    float x = lg + ((any && m == 0) ? -1e30f : 0.0f);

    sdata[n] = x;
    __syncthreads();
    for (int s = NN / 2; s > 0; s >>= 1) {
        if (n < s) sdata[n] = fmaxf(sdata[n], sdata[n + s]);
        __syncthreads();
    }
    float mx = sdata[0];
    __syncthreads();

    float e = __expf(x - mx);
    sdata[n] = e;
    __syncthreads();
    for (int s = NN / 2; s > 0; s >>= 1) {
        if (n < s) sdata[n] += sdata[n + s];
        __syncthreads();
    }
    float wgt = e / sdata[0];
    if (!any) wgt = 0.0f;
    g_weights[b * NN + n] = wgt;
}

// ---------------------------------------------------------------------------
// context[b, d] = sum_n weights[b, n] * mv[b, n, d]   (fp32 mv, full accuracy)
// ---------------------------------------------------------------------------
__global__ __launch_bounds__(256) void context_kernel(const float* __restrict__ mv,
                                                      float* __restrict__ out) {
    __shared__ float ws[256];
    const int b  = blockIdx.y;
    const int d  = blockIdx.x * 256 + threadIdx.x;
    const int n0 = blockIdx.z * 256;

    ws[threadIdx.x] = g_weights[b * NN + n0 + threadIdx.x];
    __syncthreads();

    const float* base = mv + ((size_t)b * NN + n0) * MD + d;
    float acc = 0.f;
#pragma unroll 8
    for (int n = 0; n < 256; n++)
        acc += ws[n] * base[(size_t)n * MD];

    atomicAdd(&out[b * AD + d], acc);
}

// ---------------------------------------------------------------------------
extern "C" void kernel_launch(void* const* d_in, const int* in_sizes, int n_in,
                              void* d_out, int out_size) {
    const float* mv    = (const float*)d_in[0];  // (64, 512, 1024)
    const int*   mask  = (const int*)  d_in[1];  // (64, 512)
    const float* query = (const float*)d_in[2];  // (64, 1024)
    const float* Wh    = (const float*)d_in[3];  // (1024, 1024)
    const float* Ws    = (const float*)d_in[4];  // (1024, 1024)
    const float* v     = (const float*)d_in[5];  // (1024, 1)
    float* out = (float*)d_out;                  // (64, 1024)

    cudaFuncSetAttribute(gemm_hmma_kernel,
                         cudaFuncAttributeMaxDynamicSharedMemorySize, SMEM_TOTAL);

    zero_kernel<<<(BB * AD + 255) / 256, 256>>>(out);
    convert_mv_kernel<<<(int)((size_t)ROWS * MD / 1024), 256>>>(mv);
    whT_convert_kernel<<<dim3(32, 32), dim3(32, 8)>>>(Wh);
    tq_kernel<<<dim3(8, 16), 256>>>(query, Ws);

    // x = N tiles (fast) so a wave shares A tiles through L2
    gemm_hmma_kernel<<<dim3(AD / NT, ROWS / MT), 128, SMEM_TOTAL>>>(v);

    softmax_kernel<<<BB, NN>>>(mask);
    context_kernel<<<dim3(AD / 256, BB, 2), 256>>>(mv, out);
}

// round 14
// speedup vs baseline: 1.1436x; 1.1436x over previous
#include <cuda_runtime.h>
#include <cuda_fp16.h>
#include <cstdint>
#include <math.h>

// ---------------- problem dims ----------------
#define BB   64
#define NN   512
#define MD   1024
#define AD   1024
#define ROWS (BB * NN)          // 32768

// ---------------- GEMM tiling ----------------
#define MT 128                  // M per CTA
#define NT 128                  // N per CTA
#define KC 64                   // K elems per chunk (64 fp16 = 128 B rows)
#define NCHUNK (MD / KC)        // 16

// stage: A 16K | B 16K
#define ST_A  0
#define ST_B  16384
#define STAGE_BYTES 32768
#define NSTAGE 3
#define SMEM_TOTAL (NSTAGE * STAGE_BYTES)   // 96 KB, 2 CTAs/SM

// XOR swizzle for 128-byte rows (conflict-free ldmatrix + cp.async stores)
#define SWZ(x) ((x) ^ (((x) >> 3) & 0x70))

// ---------------- scratch (__device__ globals; no allocs allowed) ----------
__device__ float g_tq[BB * AD];
__device__ float g_logits[ROWS];
__device__ float g_weights[ROWS];
__device__ __half g_Ah[(size_t)ROWS * MD];   // mv rounded to fp16
__device__ __half g_Bh[(size_t)AD * MD];     // Wh^T rounded to fp16, [n][k]

// ---------------- PTX helpers (plain-sm_103-legal) ----------------
__device__ __forceinline__ uint32_t smem_u32(const void* p) {
    uint32_t a;
    asm("{ .reg .u64 t; cvta.to.shared.u64 t, %1; cvt.u32.u64 %0, t; }"
        : "=r"(a) : "l"(p));
    return a;
}
__device__ __forceinline__ void cp16(uint32_t s, const void* g) {
    asm volatile("cp.async.cg.shared.global [%0], [%1], 16;" :: "r"(s), "l"(g));
}
#define CP_COMMIT() asm volatile("cp.async.commit_group;" ::: "memory")
#define CP_WAIT2()  asm volatile("cp.async.wait_group %0;" :: "n"(2) : "memory")

#define LDSM4(r, a) \
    asm volatile("ldmatrix.sync.aligned.m8n8.x4.shared.b16 {%0,%1,%2,%3}, [%4];" \
        : "=r"((r)[0]), "=r"((r)[1]), "=r"((r)[2]), "=r"((r)[3]) : "r"(a))

#define MMA16816(d, a, b0v, b1v) \
    asm volatile("mma.sync.aligned.m16n8k16.row.col.f32.f16.f16.f32 " \
        "{%0,%1,%2,%3}, {%4,%5,%6,%7}, {%8,%9}, {%0,%1,%2,%3};" \
        : "+f"((d)[0]), "+f"((d)[1]), "+f"((d)[2]), "+f"((d)[3]) \
        : "r"((a)[0]), "r"((a)[1]), "r"((a)[2]), "r"((a)[3]), \
          "r"(b0v), "r"(b1v))

// ---------------------------------------------------------------------------
// Zero init: logits, tq (both atomic-accumulated), d_out (poisoned)
// ---------------------------------------------------------------------------
__global__ void zero_kernel(float* __restrict__ ctx) {
    int i = blockIdx.x * blockDim.x + threadIdx.x;   // 0 .. 65535
    if (i < ROWS) g_logits[i] = 0.0f;
    if (i < BB * AD) { g_tq[i] = 0.0f; ctx[i] = 0.0f; }
}

// ---------------------------------------------------------------------------
// fp32 -> fp16 round of mv
// ---------------------------------------------------------------------------
__global__ __launch_bounds__(256) void convert_mv_kernel(const float* __restrict__ mv) {
    size_t i = ((size_t)blockIdx.x * 256 + threadIdx.x) * 4;
    float4 x = *reinterpret_cast<const float4*>(mv + i);
    __half2* d = reinterpret_cast<__half2*>(g_Ah + i);
    d[0] = __floats2half2_rn(x.x, x.y);
    d[1] = __floats2half2_rn(x.z, x.w);
}

// ---------------------------------------------------------------------------
// Wh [k][n] -> Wh^T fp16 [n][k] via smem tile transpose
// ---------------------------------------------------------------------------
__global__ void whT_convert_kernel(const float* __restrict__ Wh) {
    __shared__ float t[32][33];
    int n0 = blockIdx.x * 32, k0 = blockIdx.y * 32;
    int tx = threadIdx.x, ty = threadIdx.y;          // block (32, 8)
    for (int i = ty; i < 32; i += 8)
        t[i][tx] = Wh[(size_t)(k0 + i) * AD + n0 + tx];
    __syncthreads();
    for (int i = ty; i < 32; i += 8) {
        float x = t[tx][i];                          // Wh[k0+tx][n0+i]
        g_Bh[(size_t)(n0 + i) * MD + k0 + tx] = __float2half_rn(x);
    }
}

// ---------------------------------------------------------------------------
// tq = query @ Ws.  Grid (32 k-chunks of 32, 32 batch-PAIRS) = 1024 CTAs
// (same parallelism as the proven R11 version) but each Ws slice is read
// once for TWO batches -> Ws L2 traffic 256 MB -> 128 MB.
// ---------------------------------------------------------------------------
__global__ __launch_bounds__(256) void tq_kernel(const float* __restrict__ q,
                                                 const float* __restrict__ Ws) {
    __shared__ float qs[2][32];
    const int k0 = blockIdx.x * 32;
    const int b0 = blockIdx.y * 2;
    if (threadIdx.x < 64)
        qs[threadIdx.x >> 5][threadIdx.x & 31] =
            q[(b0 + (threadIdx.x >> 5)) * MD + k0 + (threadIdx.x & 31)];
    __syncthreads();

    const int c = threadIdx.x;               // cols c, c+256, c+512, c+768
    float a00 = 0.f, a01 = 0.f, a02 = 0.f, a03 = 0.f;
    float a10 = 0.f, a11 = 0.f, a12 = 0.f, a13 = 0.f;
#pragma unroll 8
    for (int k = 0; k < 32; k++) {
        const float* wrow = Ws + (size_t)(k0 + k) * AD + c;
        float w0 = wrow[0], w1 = wrow[256], w2 = wrow[512], w3 = wrow[768];
        float q0 = qs[0][k], q1 = qs[1][k];
        a00 += q0 * w0; a01 += q0 * w1; a02 += q0 * w2; a03 += q0 * w3;
        a10 += q1 * w0; a11 += q1 * w1; a12 += q1 * w2; a13 += q1 * w3;
    }
    float* d0 = g_tq + b0 * AD + c;
    atomicAdd(d0,       a00); atomicAdd(d0 + 256, a01);
    atomicAdd(d0 + 512, a02); atomicAdd(d0 + 768, a03);
    float* d1 = g_tq + (b0 + 1) * AD + c;
    atomicAdd(d1,       a10); atomicAdd(d1 + 256, a11);
    atomicAdd(d1 + 512, a12); atomicAdd(d1 + 768, a13);
}

// ---------------------------------------------------------------------------
// Big GEMM on HMMA fp16 (fp32 accum), single-term: D = Ah @ Bh^T.
// Fused epilogue: logits[m] += sum_n tanh(D + tq) * v[n].
// CTA 128x128, 8 warps (warp tile 64x32), 16 K-chunks of 64,
// 3-stage cp.async pipeline, SW128-swizzled smem, ldmatrix operand fetch.
// (Exact R11 configuration — proven 277us total.)
// ---------------------------------------------------------------------------
__global__ __launch_bounds__(256, 2) void gemm_hmma_kernel(const float* __restrict__ v) {
    extern __shared__ char smem[];
    const uint32_t sb = smem_u32(smem);
    const int tid  = threadIdx.x;
    const int lane = tid & 31;
    const int w    = tid >> 5;
    const int tileN = blockIdx.x * NT;
    const int tileM = blockIdx.y * MT;

    const __half* Ag = g_Ah + (size_t)tileM * MD;
    const __half* Bg = g_Bh + (size_t)tileN * MD;

    // cp.async per-thread coords
    const int cr = tid >> 3;            // 0..31 (+32 per rep)
    const int cc = tid & 7;             // 16B unit in 128B row

    // ldmatrix invariants
    const int lrow = lane & 15;
    const int lkb  = (lane >> 4) * 16;

    // warp tile position
    const int wm = (w >> 2) * 64;
    const int wn = (w & 3) * 32;

    float acc[4][4][4];
#pragma unroll
    for (int i = 0; i < 4; i++)
#pragma unroll
        for (int j = 0; j < 4; j++)
#pragma unroll
            for (int c = 0; c < 4; c++) acc[i][j][c] = 0.f;

    auto issue_copy = [&](int chunk) {
        const int k0 = chunk * KC;
        const uint32_t st = sb + (chunk % NSTAGE) * STAGE_BYTES;
#pragma unroll
        for (int i = 0; i < 4; i++) {
            const int r = cr + i * 32;
            const uint32_t so = SWZ((uint32_t)(r * 128 + cc * 16));
            const size_t go = (size_t)r * MD + k0 + cc * 8;
            cp16(st + ST_A + so, Ag + go);
            cp16(st + ST_B + so, Bg + go);
        }
    };

    issue_copy(0); CP_COMMIT();
    issue_copy(1); CP_COMMIT();

    for (int c = 0; c < NCHUNK; ++c) {
        if (c + 2 < NCHUNK) issue_copy(c + 2);
        CP_COMMIT();
        CP_WAIT2();
        __syncthreads();

        const uint32_t st = sb + (c % NSTAGE) * STAGE_BYTES;
#pragma unroll
        for (int ks = 0; ks < 4; ks++) {
            const int kb2 = ks * 32 + lkb;
            uint32_t a[4][4], b[2][4];
#pragma unroll
            for (int i = 0; i < 4; i++) {
                uint32_t ad = st + ST_A + SWZ((uint32_t)((wm + i * 16 + lrow) * 128 + kb2));
                LDSM4(a[i], ad);
            }
#pragma unroll
            for (int j = 0; j < 2; j++) {
                uint32_t ad = st + ST_B + SWZ((uint32_t)((wn + j * 16 + lrow) * 128 + kb2));
                LDSM4(b[j], ad);
            }
#pragma unroll
            for (int i = 0; i < 4; i++) {
                MMA16816(acc[i][0], a[i], b[0][0], b[0][2]);
                MMA16816(acc[i][1], a[i], b[0][1], b[0][3]);
                MMA16816(acc[i][2], a[i], b[1][0], b[1][2]);
                MMA16816(acc[i][3], a[i], b[1][1], b[1][3]);
            }
        }
        __syncthreads();
    }

    // ---- fused epilogue: logits[m] += sum_n tanh(acc + tq[b][n]) * v[n] ----
    const int bq = (tileM / NN) * AD;
    const int rq = lane >> 2;
    const int cq = (lane & 3) * 2;

#pragma unroll
    for (int i = 0; i < 4; i++) {
        float s0 = 0.f, s1 = 0.f;
#pragma unroll
        for (int j = 0; j < 4; j++) {
            const int n0 = tileN + wn + j * 8 + cq;
            const float v0 = v[n0],          v1 = v[n0 + 1];
            const float t0 = g_tq[bq + n0],  t1 = g_tq[bq + n0 + 1];
            s0 += tanhf(acc[i][j][0] + t0) * v0 + tanhf(acc[i][j][1] + t1) * v1;
            s1 += tanhf(acc[i][j][2] + t0) * v0 + tanhf(acc[i][j][3] + t1) * v1;
        }
        s0 += __shfl_xor_sync(0xffffffffu, s0, 1);
        s0 += __shfl_xor_sync(0xffffffffu, s0, 2);
        s1 += __shfl_xor_sync(0xffffffffu, s1, 1);
        s1 += __shfl_xor_sync(0xffffffffu, s1, 2);
        if ((lane & 3) == 0) {
            const int m0 = tileM + wm + i * 16 + rq;
            atomicAdd(&g_logits[m0],     s0);
            atomicAdd(&g_logits[m0 + 8], s1);
        }
    }
}

// ---------------------------------------------------------------------------
// Masked softmax (reference semantics incl. fully-masked rows)
// ---------------------------------------------------------------------------
__global__ __launch_bounds__(NN) void softmax_kernel(const int* __restrict__ mask) {
    __shared__ float sdata[NN];
    int b = blockIdx.x, n = threadIdx.x;
    float lg = g_logits[b * NN + n];
    int   m  = mask[b * NN + n];

    int any = __syncthreads_or(m != 0);
    float x = lg + ((any && m == 0) ? -1e30f : 0.0f);

    sdata[n] = x;
    __syncthreads();
    for (int s = NN / 2; s > 0; s >>= 1) {
        if (n < s) sdata[n] = fmaxf(sdata[n], sdata[n + s]);
        __syncthreads();
    }
    float mx = sdata[0];
    __syncthreads();

    float e = __expf(x - mx);
    sdata[n] = e;
    __syncthreads();
    for (int s = NN / 2; s > 0; s >>= 1) {
        if (n < s) sdata[n] += sdata[n + s];
        __syncthreads();
    }
    float wgt = e / sdata[0];
    if (!any) wgt = 0.0f;
    g_weights[b * NN + n] = wgt;
}

// ---------------------------------------------------------------------------
// context[b, d] = sum_n weights[b, n] * mv_fp16[b, n, d]
// Reads the fp16 copy (g_Ah): half the HBM traffic of fp32 mv.
// grid (2 d-chunks of 512 halves, 64 b, 4 n-quarters); half2 loads.
// ---------------------------------------------------------------------------
__global__ __launch_bounds__(256) void context_kernel(float* __restrict__ out) {
    __shared__ float ws[128];
    const int b  = blockIdx.y;
    const int d2 = blockIdx.x * 256 + threadIdx.x;   // half2 index (0..511)
    const int n0 = blockIdx.z * 128;

    if (threadIdx.x < 128) ws[threadIdx.x] = g_weights[b * NN + n0 + threadIdx.x];
    __syncthreads();

    const __half2* base = reinterpret_cast<const __half2*>(g_Ah)
                        + ((size_t)b * NN + n0) * (MD / 2) + d2;
    float a0 = 0.f, a1 = 0.f;
#pragma unroll 8
    for (int n = 0; n < 128; n++) {
        float2 x = __half22float2(base[(size_t)n * (MD / 2)]);
        float wv = ws[n];
        a0 += wv * x.x;
        a1 += wv * x.y;
    }
    atomicAdd(&out[b * AD + 2 * d2],     a0);
    atomicAdd(&out[b * AD + 2 * d2 + 1], a1);
}

// ---------------------------------------------------------------------------
extern "C" void kernel_launch(void* const* d_in, const int* in_sizes, int n_in,
                              void* d_out, int out_size) {
    const float* mv    = (const float*)d_in[0];  // (64, 512, 1024)
    const int*   mask  = (const int*)  d_in[1];  // (64, 512)
    const float* query = (const float*)d_in[2];  // (64, 1024)
    const float* Wh    = (const float*)d_in[3];  // (1024, 1024)
    const float* Ws    = (const float*)d_in[4];  // (1024, 1024)
    const float* v     = (const float*)d_in[5];  // (1024, 1)
    float* out = (float*)d_out;                  // (64, 1024)

    cudaFuncSetAttribute(gemm_hmma_kernel,
                         cudaFuncAttributeMaxDynamicSharedMemorySize, SMEM_TOTAL);

    zero_kernel<<<(BB * AD + 255) / 256, 256>>>(out);
    convert_mv_kernel<<<(int)((size_t)ROWS * MD / 1024), 256>>>(mv);
    whT_convert_kernel<<<dim3(32, 32), dim3(32, 8)>>>(Wh);
    tq_kernel<<<dim3(32, 32), 256>>>(query, Ws);

    // x = N tiles (fast) so a wave shares A tiles through L2
    gemm_hmma_kernel<<<dim3(AD / NT, ROWS / MT), 256, SMEM_TOTAL>>>(v);

    softmax_kernel<<<BB, NN>>>(mask);
    context_kernel<<<dim3(2, BB, 4), 256>>>(out);
}